// round 5
// baseline (speedup 1.0000x reference)
#include <cuda_runtime.h>
#include <math.h>

#define T_LEN 1024
#define NN    1022            /* templates */
#define PAD   1088            /* max smem read index < 1060 */
#define RR    0.2f
#define NTHR  768

__device__ float g_ent[128];
__device__ unsigned int g_barrier;

// One 32-k chunk of 8 consecutive diagonals dbase..dbase+7 (dbase ≡ 1 mod 8).
// MSB-first insertion: pair k of the chunk lands at bit (31-k).
// Bit = sign(|xa-xb| - Rs): match <=> negative.
__device__ __forceinline__ void chunk_mask8(const float* __restrict__ xs, int k0, int dbase,
                                            float Rs, unsigned int m[8]) {
    const float4* __restrict__ xa4 = reinterpret_cast<const float4*>(xs + k0);
    const float4* __restrict__ w4  = reinterpret_cast<const float4*>(xs + k0 + dbase - 1);
    unsigned int acc[8] = {0, 0, 0, 0, 0, 0, 0, 0};
    float w[12];
    float4 t0 = w4[0];
    float4 t1 = w4[1];
    w[0] = t0.x; w[1] = t0.y; w[2]  = t0.z; w[3]  = t0.w;
    w[4] = t1.x; w[5] = t1.y; w[6]  = t1.z; w[7]  = t1.w;
    #pragma unroll
    for (int q = 0; q < 8; q++) {
        float4 a  = xa4[q];
        float4 tn = w4[q + 2];
        w[8] = tn.x; w[9] = tn.y; w[10] = tn.z; w[11] = tn.w;
        float av[4] = {a.x, a.y, a.z, a.w};
        #pragma unroll
        for (int r = 0; r < 4; r++) {
            #pragma unroll
            for (int s = 0; s < 8; s++) {
                float u = fabsf(av[r] - w[1 + s + r]) - Rs;
                acc[s] = __funnelshift_l(__float_as_uint(u), acc[s], 1);
            }
        }
        w[0] = w[4]; w[1] = w[5]; w[2] = w[6]; w[3] = w[7];
        w[4] = w[8]; w[5] = w[9]; w[6] = w[10]; w[7] = w[11];
    }
    #pragma unroll
    for (int s = 0; s < 8; s++) m[s] = acc[s];
}

// Count m/m1 matches over chunks [c0, c1) of diagonals dbase..dbase+7.
// Diagonal s has (Lbase - s) valid pairs (clamped at 0). MSB-first order:
//   successor bit sits one position lower -> S = funnelshift_l(Bnext, Bcur, sh).
__device__ __forceinline__ void process_range(const float* __restrict__ xs,
                                              int dbase, int Lbase, int c0, int c1, float Rs,
                                              unsigned int& cm, unsigned int& cm1) {
    if (c0 >= c1) return;
    unsigned int Bc[8], Bn[8];
    chunk_mask8(xs, 32 * c0, dbase, Rs, Bc);
    for (int c = c0; c < c1; c++) {
        chunk_mask8(xs, 32 * (c + 1), dbase, Rs, Bn);
        const int remBase = Lbase - 32 * c;
        #pragma unroll
        for (int s = 0; s < 8; s++) {
            int rem = remBase - s;
            unsigned int mask = (rem >= 32) ? 0xffffffffu
                              : ((rem <= 0) ? 0u : (0xffffffffu << (32 - rem)));
            unsigned int S1 = __funnelshift_l(Bn[s], Bc[s], 1);
            unsigned int S2 = __funnelshift_l(Bn[s], Bc[s], 2);
            unsigned int mm = Bc[s] & S1 & mask;
            cm  += __popc(mm);
            cm1 += __popc(mm & S2);
            Bc[s] = Bn[s];
        }
    }
}

__global__ __launch_bounds__(NTHR, 1)
void sampen_kernel(const float* __restrict__ pred, const float* __restrict__ tgt,
                   float* __restrict__ out) {
    __shared__ __align__(16) float xs[PAD];
    __shared__ double redA[24], redB[24];
    __shared__ unsigned int redc[24], redc1[24];
    __shared__ float s_thresh;

    const int s   = blockIdx.x;
    const int tid = threadIdx.x;
    const float* src = (s < 64) ? (pred + (size_t)s * T_LEN)
                                : (tgt  + (size_t)(s - 64) * T_LEN);

    // ---- load raw signal + zero pad ----
    float v0 = src[tid];
    float v1 = (tid + NTHR < T_LEN) ? src[tid + NTHR] : 0.0f;
    xs[tid] = v0;
    if (tid + NTHR < T_LEN) xs[tid + NTHR] = v1;
    for (int i = T_LEN + tid; i < PAD; i += NTHR) xs[i] = 0.0f;

    // ---- std (ddof=1) in double; mean cancels inside |xi-xj|:
    //      scaled threshold Rs = R * (std + eps) ----
    double ls  = (double)v0 + (double)v1;
    double ls2 = (double)v0 * (double)v0 + (double)v1 * (double)v1;
    #pragma unroll
    for (int o = 16; o > 0; o >>= 1) {
        ls  += __shfl_down_sync(0xffffffffu, ls,  o);
        ls2 += __shfl_down_sync(0xffffffffu, ls2, o);
    }
    if ((tid & 31) == 0) { redA[tid >> 5] = ls; redB[tid >> 5] = ls2; }
    __syncthreads();
    if (tid == 0) {
        double S = 0.0, S2 = 0.0;
        #pragma unroll
        for (int w = 0; w < 24; w++) { S += redA[w]; S2 += redB[w]; }
        double var = (S2 - S * S / (double)T_LEN) / (double)(T_LEN - 1);
        double sd  = sqrt(var);
        s_thresh = (float)((double)RR * (sd + 1e-8));
    }
    __syncthreads();
    const float Rs = s_thresh;

    // ---- upper-triangle counting: 8-diagonal groups, paired + 12-way split-k ----
    // Group g covers diagonals 8g+1..8g+8, g in [0,128); overflow diagonals mask to 0.
    // Pair (P, 127-P): total chunks C_A + C_B == 33 for every P (remainders never 0).
    // Thread = (P = tid & 63, slot = tid >> 6); slot owns [g0, g1) of the 33 chunks.
    const int P  = tid & 63;
    const int sg = tid >> 6;           // 0..11, warp-uniform
    const int dA = 8 * P + 1;
    const int LA = NN - dA;            // 1021 - 8P
    const int dB = 1017 - 8 * P;       // group 127-P
    const int LB = NN - dB;            // 5 + 8P
    const int CA = (LA + 31) >> 5;
    const int g0 = (sg * 33) / 12;
    const int g1 = ((sg + 1) * 33) / 12;

    unsigned int cm = 0, cm1 = 0;
    {
        int a0 = g0, a1 = (g1 < CA) ? g1 : CA;
        process_range(xs, dA, LA, a0, a1, Rs, cm, cm1);
        int b0 = (g0 > CA ? g0 : CA) - CA;
        int b1 = g1 - CA;
        process_range(xs, dB, LB, b0, b1, Rs, cm, cm1);
    }

    // ---- reduce counts ----
    #pragma unroll
    for (int o = 16; o > 0; o >>= 1) {
        cm  += __shfl_down_sync(0xffffffffu, cm,  o);
        cm1 += __shfl_down_sync(0xffffffffu, cm1, o);
    }
    if ((tid & 31) == 0) { redc[tid >> 5] = cm; redc1[tid >> 5] = cm1; }
    __syncthreads();

    if (tid == 0) {
        unsigned int tm = 0, tm1 = 0;
        #pragma unroll
        for (int w = 0; w < 24; w++) { tm += redc[w]; tm1 += redc1[w]; }
        // symmetric matrix + zero diagonal: matches = NN + 2*upper
        unsigned int matches_m  = (unsigned int)NN + 2u * tm;
        unsigned int matches_m1 = (unsigned int)NN + 2u * tm1;
        float ratio = (float)matches_m1 / (float)matches_m;   // matches_m >= NN > 0
        ratio = fmaxf(ratio, 1e-30f);
        g_ent[s] = -logf(ratio);

        // ---- fused finalize: last block computes the MSE ----
        __threadfence();
        unsigned int old = atomicAdd(&g_barrier, 1);
        if (old == 127u) {
            g_barrier = 0;            // reset for next graph replay
            __threadfence();          // make all g_ent writes visible
            float acc = 0.0f;
            #pragma unroll
            for (int i = 0; i < 64; i++) {
                float dp = __ldcg(&g_ent[i]);
                float dt = __ldcg(&g_ent[64 + i]);
                float dd = dp - dt;
                acc += dd * dd;
            }
            out[0] = acc * (1.0f / 64.0f);
        }
    }
}

extern "C" void kernel_launch(void* const* d_in, const int* in_sizes, int n_in,
                              void* d_out, int out_size) {
    const float* pred = (const float*)d_in[0];
    const float* tgt  = (const float*)d_in[1];
    float* out = (float*)d_out;
    sampen_kernel<<<128, NTHR>>>(pred, tgt, out);
}

// round 6
// speedup vs baseline: 1.0584x; 1.0584x over previous
#include <cuda_runtime.h>
#include <math.h>

#define T_LEN 1024
#define NN    1022            /* templates */
#define PAD   1096            /* max smem read index is 1087 */
#define RR    0.2f

__device__ float g_ent[128];
__device__ unsigned int g_barrier;

// One 32-k chunk of 4 consecutive diagonals dbase..dbase+3 (dbase ≡ 1 mod 4).
// MSB-first insertion: pair k of the chunk lands at bit (31-k).
// Bit = sign( (a-b)^2 - Rs^2 ) : match <=> negative. 3 fixed-lat ops per pair:
//   FADD t = a-b ; FFMA u = t*t - Rs2 ; SHF acc = (acc<<1)|(u>>31)
__device__ __forceinline__ void chunk_mask4(const float* __restrict__ xs, int k0, int dbase,
                                            float Rs2, unsigned int m[4]) {
    const float4* __restrict__ xa4 = reinterpret_cast<const float4*>(xs + k0);
    const float4* __restrict__ w4  = reinterpret_cast<const float4*>(xs + k0 + dbase - 1);
    unsigned int a0 = 0, a1 = 0, a2 = 0, a3 = 0;
    float w[8];
    float4 t0 = w4[0];
    w[0] = t0.x; w[1] = t0.y; w[2] = t0.z; w[3] = t0.w;
    #pragma unroll
    for (int q = 0; q < 8; q++) {
        float4 a  = xa4[q];
        float4 tn = w4[q + 1];
        w[4] = tn.x; w[5] = tn.y; w[6] = tn.z; w[7] = tn.w;
        float av[4] = {a.x, a.y, a.z, a.w};
        #pragma unroll
        for (int r = 0; r < 4; r++) {
            float d0 = av[r] - w[r + 1];
            float d1 = av[r] - w[r + 2];
            float d2 = av[r] - w[r + 3];
            float d3 = av[r] - w[r + 4];
            float u0 = fmaf(d0, d0, -Rs2);
            float u1 = fmaf(d1, d1, -Rs2);
            float u2 = fmaf(d2, d2, -Rs2);
            float u3 = fmaf(d3, d3, -Rs2);
            a0 = __funnelshift_l(__float_as_uint(u0), a0, 1);
            a1 = __funnelshift_l(__float_as_uint(u1), a1, 1);
            a2 = __funnelshift_l(__float_as_uint(u2), a2, 1);
            a3 = __funnelshift_l(__float_as_uint(u3), a3, 1);
        }
        w[0] = w[4]; w[1] = w[5]; w[2] = w[6]; w[3] = w[7];
    }
    m[0] = a0; m[1] = a1; m[2] = a2; m[3] = a3;
}

// Count m/m1 matches for chunks [c0, c1) of diagonals dbase..dbase+3.
// Diagonal s has Lbase - s valid pairs. MSB-first bit order:
//   successor bit sits one position lower -> S = funnelshift_l(Bnext, Bcur, sh).
__device__ __forceinline__ void process_range(const float* __restrict__ xs,
                                              int dbase, int Lbase, int c0, int c1, float Rs2,
                                              unsigned int& cm, unsigned int& cm1) {
    if (c0 >= c1) return;
    unsigned int Bc[4], Bn[4];
    chunk_mask4(xs, 32 * c0, dbase, Rs2, Bc);
    for (int c = c0; c < c1; c++) {
        chunk_mask4(xs, 32 * (c + 1), dbase, Rs2, Bn);
        if (32 * c + 35 <= Lbase) {          // all 4 diagonals full in this chunk
            #pragma unroll
            for (int s = 0; s < 4; s++) {
                unsigned int S1 = __funnelshift_l(Bn[s], Bc[s], 1);
                unsigned int S2 = __funnelshift_l(Bn[s], Bc[s], 2);
                unsigned int mm = Bc[s] & S1;
                cm  += __popc(mm);
                cm1 += __popc(mm & S2);
            }
        } else {                              // diagonal-end chunk: keep top `rem` bits
            #pragma unroll
            for (int s = 0; s < 4; s++) {
                int rem = Lbase - s - 32 * c;
                unsigned int mask = (rem >= 32) ? 0xffffffffu
                                  : ((rem <= 0) ? 0u : (0xffffffffu << (32 - rem)));
                unsigned int S1 = __funnelshift_l(Bn[s], Bc[s], 1);
                unsigned int S2 = __funnelshift_l(Bn[s], Bc[s], 2);
                unsigned int mm = Bc[s] & S1 & mask;
                cm  += __popc(mm);
                cm1 += __popc(mm & S2);
            }
        }
        Bc[0] = Bn[0]; Bc[1] = Bn[1]; Bc[2] = Bn[2]; Bc[3] = Bn[3];
    }
}

__global__ __launch_bounds__(1024, 1)
void sampen_kernel(const float* __restrict__ pred, const float* __restrict__ tgt,
                   float* __restrict__ out) {
    __shared__ __align__(16) float xs[PAD];
    __shared__ double redA[32], redB[32];
    __shared__ unsigned int redc[32], redc1[32];
    __shared__ float s_thresh2;

    const int s   = blockIdx.x;
    const int tid = threadIdx.x;
    const float* src = (s < 64) ? (pred + (size_t)s * T_LEN)
                                : (tgt  + (size_t)(s - 64) * T_LEN);

    // ---- load raw signal + zero pad ----
    float v = src[tid];
    xs[tid] = v;
    for (int i = T_LEN + tid; i < PAD; i += 1024) xs[i] = 0.0f;

    // ---- std (ddof=1) in double; mean cancels inside |xi-xj|:
    //      squared scaled threshold Rs2 = (R*(std+eps))^2 ----
    double ls  = (double)v;
    double ls2 = (double)v * (double)v;
    #pragma unroll
    for (int o = 16; o > 0; o >>= 1) {
        ls  += __shfl_down_sync(0xffffffffu, ls,  o);
        ls2 += __shfl_down_sync(0xffffffffu, ls2, o);
    }
    if ((tid & 31) == 0) { redA[tid >> 5] = ls; redB[tid >> 5] = ls2; }
    __syncthreads();
    if (tid == 0) {
        double S = 0.0, S2 = 0.0;
        #pragma unroll
        for (int w = 0; w < 32; w++) { S += redA[w]; S2 += redB[w]; }
        double var = (S2 - S * S / (double)T_LEN) / (double)(T_LEN - 1);
        double sd  = sqrt(var);
        double rs  = (double)RR * (sd + 1e-8);
        s_thresh2  = (float)(rs * rs);
    }
    __syncthreads();
    const float Rs2 = s_thresh2;

    // ---- upper-triangle counting: 4-diagonal groups, paired + 8-way split-k ----
    // Group g covers diagonals 4g+1..4g+4. Pair (P, 255-P): C_A + C_B == 33 chunks.
    // Thread = (P = tid & 127, slot = tid >> 7); slot owns [g0, g1) of the 33 chunks.
    const int P  = tid & 127;
    const int sg = tid >> 7;
    const int dA = 4 * P + 1;
    const int LA = NN - dA;            // 1021 - 4P
    const int dB = 1021 - 4 * P;       // group 255-P
    const int LB = NN - dB;            // 4P + 1
    const int CA = (LA + 31) >> 5;
    const int C  = CA + ((LB + 31) >> 5);   // == 33
    const int g0 = (sg * C) >> 3;
    const int g1 = ((sg + 1) * C) >> 3;

    unsigned int cm = 0, cm1 = 0;
    {
        int a0 = g0, a1 = (g1 < CA) ? g1 : CA;
        process_range(xs, dA, LA, a0, a1, Rs2, cm, cm1);
        int b0 = (g0 > CA ? g0 : CA) - CA;
        int b1 = g1 - CA;
        process_range(xs, dB, LB, b0, b1, Rs2, cm, cm1);
    }

    // ---- reduce counts ----
    #pragma unroll
    for (int o = 16; o > 0; o >>= 1) {
        cm  += __shfl_down_sync(0xffffffffu, cm,  o);
        cm1 += __shfl_down_sync(0xffffffffu, cm1, o);
    }
    if ((tid & 31) == 0) { redc[tid >> 5] = cm; redc1[tid >> 5] = cm1; }
    __syncthreads();

    if (tid == 0) {
        unsigned int tm = 0, tm1 = 0;
        #pragma unroll
        for (int w = 0; w < 32; w++) { tm += redc[w]; tm1 += redc1[w]; }
        // symmetric matrix + zero diagonal: matches = NN + 2*upper
        unsigned int matches_m  = (unsigned int)NN + 2u * tm;
        unsigned int matches_m1 = (unsigned int)NN + 2u * tm1;
        float ratio = (float)matches_m1 / (float)matches_m;   // matches_m >= NN > 0
        ratio = fmaxf(ratio, 1e-30f);
        g_ent[s] = -logf(ratio);

        // ---- fused finalize: last block computes the MSE ----
        __threadfence();
        unsigned int old = atomicAdd(&g_barrier, 1);
        if (old == 127u) {
            g_barrier = 0;            // reset for next graph replay
            __threadfence();          // make all g_ent writes visible
            float acc = 0.0f;
            #pragma unroll
            for (int i = 0; i < 64; i++) {
                float dp = __ldcg(&g_ent[i]);
                float dt = __ldcg(&g_ent[64 + i]);
                float dd = dp - dt;
                acc += dd * dd;
            }
            out[0] = acc * (1.0f / 64.0f);
        }
    }
}

extern "C" void kernel_launch(void* const* d_in, const int* in_sizes, int n_in,
                              void* d_out, int out_size) {
    const float* pred = (const float*)d_in[0];
    const float* tgt  = (const float*)d_in[1];
    float* out = (float*)d_out;
    sampen_kernel<<<128, 1024>>>(pred, tgt, out);
}

// round 7
// speedup vs baseline: 1.1571x; 1.0932x over previous
#include <cuda_runtime.h>
#include <math.h>

#define T_LEN 1024
#define NN    1022            /* templates */
#define PAD   1096            /* max smem read index is 1090 */
#define RR    0.2f

__device__ float g_ent[128];
__device__ unsigned int g_barrier;

// Self-contained unit: chunk c (k = k0..k0+31) of 4 diagonals dbase..dbase+3.
// Computes 34 booleans per diagonal (j = 0..33) so neighbor bits b_{k+1}, b_{k+2}
// never cross units. MSB-first: acc bit (31-j) = b_j; ext bit31 = b_32, bit30 = b_33.
// Bit = sign( (a-b)^2 - Rs2 ): FADD + FFMA + SHF, branchless throughout.
// remBase = Lbase - k0 (may be <=0 for overflow diagonals -> mask 0).
__device__ __forceinline__ void unit_count(const float* __restrict__ xs, int k0, int dbase,
                                           int remBase, float Rs2,
                                           unsigned int& cm, unsigned int& cm1) {
    const float4* __restrict__ xa4 = reinterpret_cast<const float4*>(xs + k0);
    const float4* __restrict__ w4  = reinterpret_cast<const float4*>(xs + k0 + dbase - 1);
    unsigned int acc[4] = {0, 0, 0, 0};
    float w[8];
    float4 t0 = w4[0];
    w[0] = t0.x; w[1] = t0.y; w[2] = t0.z; w[3] = t0.w;
    #pragma unroll
    for (int q = 0; q < 8; q++) {
        float4 a  = xa4[q];
        float4 tn = w4[q + 1];
        w[4] = tn.x; w[5] = tn.y; w[6] = tn.z; w[7] = tn.w;
        float av[4] = {a.x, a.y, a.z, a.w};
        #pragma unroll
        for (int r = 0; r < 4; r++) {
            #pragma unroll
            for (int s = 0; s < 4; s++) {
                float d = av[r] - w[1 + s + r];
                float u = fmaf(d, d, -Rs2);
                acc[s] = __funnelshift_l(__float_as_uint(u), acc[s], 1);
            }
        }
        w[0] = w[4]; w[1] = w[5]; w[2] = w[6]; w[3] = w[7];
    }
    // epilogue: j = 32, 33  (xa values x[k0+32], x[k0+33])
    // after the loop, w[0..3] hold w4[8]; flat window index 33+s -> w[1+s] / t9
    float4 a8 = xa4[8];
    float4 t9 = w4[9];
    float wx[7] = {w[0], w[1], w[2], w[3], t9.x, t9.y, t9.z};
    unsigned int ext[4];
    #pragma unroll
    for (int s = 0; s < 4; s++) {
        float d32 = a8.x - wx[1 + s];            // j=32: index 33+s
        float d33 = a8.y - wx[2 + s];            // j=33: index 34+s
        float u32 = fmaf(d32, d32, -Rs2);
        float u33 = fmaf(d33, d33, -Rs2);
        ext[s] = (__float_as_uint(u32) & 0x80000000u)
               | ((__float_as_uint(u33) >> 1) & 0x40000000u);
    }
    // count valid pairs k = k0 + j, j in [0, min(32, remBase - s))
    #pragma unroll
    for (int s = 0; s < 4; s++) {
        int rem = remBase - s;
        unsigned int mask = (rem >= 32) ? 0xffffffffu
                          : ((rem <= 0) ? 0u : (0xffffffffu << (32 - rem)));
        unsigned int S1 = __funnelshift_l(ext[s], acc[s], 1);
        unsigned int S2 = __funnelshift_l(ext[s], acc[s], 2);
        unsigned int mm = acc[s] & S1 & mask;
        cm  += __popc(mm);
        cm1 += __popc(mm & S2);
    }
}

__global__ __launch_bounds__(1024, 1)
void sampen_kernel(const float* __restrict__ pred, const float* __restrict__ tgt,
                   float* __restrict__ out) {
    __shared__ __align__(16) float xs[PAD];
    __shared__ double redA[32], redB[32];
    __shared__ unsigned int redc[32], redc1[32];
    __shared__ float s_thresh2;

    const int s   = blockIdx.x;
    const int tid = threadIdx.x;
    const float* src = (s < 64) ? (pred + (size_t)s * T_LEN)
                                : (tgt  + (size_t)(s - 64) * T_LEN);

    // ---- load raw signal + zero pad ----
    float v = src[tid];
    xs[tid] = v;
    for (int i = T_LEN + tid; i < PAD; i += 1024) xs[i] = 0.0f;

    // ---- std (ddof=1) in double; mean cancels inside |xi-xj|:
    //      squared scaled threshold Rs2 = (R*(std+eps))^2 ----
    double ls  = (double)v;
    double ls2 = (double)v * (double)v;
    #pragma unroll
    for (int o = 16; o > 0; o >>= 1) {
        ls  += __shfl_down_sync(0xffffffffu, ls,  o);
        ls2 += __shfl_down_sync(0xffffffffu, ls2, o);
    }
    if ((tid & 31) == 0) { redA[tid >> 5] = ls; redB[tid >> 5] = ls2; }
    __syncthreads();
    if (tid == 0) {
        double S = 0.0, S2 = 0.0;
        #pragma unroll
        for (int w = 0; w < 32; w++) { S += redA[w]; S2 += redB[w]; }
        double var = (S2 - S * S / (double)T_LEN) / (double)(T_LEN - 1);
        double sd  = sqrt(var);
        double rs  = (double)RR * (sd + 1e-8);
        s_thresh2  = (float)(rs * rs);
    }
    __syncthreads();
    const float Rs2 = s_thresh2;

    // ---- upper-triangle counting: 4-diagonal groups, self-contained chunk units ----
    // Pair (P, 255-P): exactly 33 units. Thread (P = tid&127, sg = tid>>7) owns
    // virtual units [g0, g1) of the 33. sg is warp-uniform -> uniform trip counts;
    // the A/B group choice per unit is a branchless per-lane select.
    const int P  = tid & 127;
    const int sg = tid >> 7;           // warp-uniform
    const int dA = 4 * P + 1;
    const int LA = NN - dA;            // 1021 - 4P
    const int dB = 1021 - 4 * P;       // partner group 255-P
    const int LB = NN - dB;            // 4P + 1
    const int CA = (LA + 31) >> 5;
    const int g0 = (sg * 33) >> 3;
    const int g1 = ((sg + 1) * 33) >> 3;

    unsigned int cm = 0, cm1 = 0;
    for (int j = g0; j < g1; j++) {
        bool inA  = (j < CA);
        int dbase = inA ? dA : dB;
        int c     = inA ? j  : j - CA;
        int Lb    = inA ? LA : LB;
        int k0    = c << 5;
        unit_count(xs, k0, dbase, Lb - k0, Rs2, cm, cm1);
    }

    // ---- reduce counts ----
    #pragma unroll
    for (int o = 16; o > 0; o >>= 1) {
        cm  += __shfl_down_sync(0xffffffffu, cm,  o);
        cm1 += __shfl_down_sync(0xffffffffu, cm1, o);
    }
    if ((tid & 31) == 0) { redc[tid >> 5] = cm; redc1[tid >> 5] = cm1; }
    __syncthreads();

    if (tid == 0) {
        unsigned int tm = 0, tm1 = 0;
        #pragma unroll
        for (int w = 0; w < 32; w++) { tm += redc[w]; tm1 += redc1[w]; }
        // symmetric matrix + zero diagonal: matches = NN + 2*upper
        unsigned int matches_m  = (unsigned int)NN + 2u * tm;
        unsigned int matches_m1 = (unsigned int)NN + 2u * tm1;
        float ratio = (float)matches_m1 / (float)matches_m;   // matches_m >= NN > 0
        ratio = fmaxf(ratio, 1e-30f);
        g_ent[s] = -logf(ratio);

        // ---- fused finalize: last block computes the MSE ----
        __threadfence();
        unsigned int old = atomicAdd(&g_barrier, 1);
        if (old == 127u) {
            g_barrier = 0;            // reset for next graph replay
            __threadfence();          // make all g_ent writes visible
            float acc = 0.0f;
            #pragma unroll
            for (int i = 0; i < 64; i++) {
                float dp = __ldcg(&g_ent[i]);
                float dt = __ldcg(&g_ent[64 + i]);
                float dd = dp - dt;
                acc += dd * dd;
            }
            out[0] = acc * (1.0f / 64.0f);
        }
    }
}

extern "C" void kernel_launch(void* const* d_in, const int* in_sizes, int n_in,
                              void* d_out, int out_size) {
    const float* pred = (const float*)d_in[0];
    const float* tgt  = (const float*)d_in[1];
    float* out = (float*)d_out;
    sampen_kernel<<<128, 1024>>>(pred, tgt, out);
}

// round 8
// speedup vs baseline: 1.2601x; 1.0890x over previous
#include <cuda_runtime.h>
#include <math.h>

#define T_LEN 1024
#define NN    1022            /* templates */
#define PAD   1104            /* max smem read index ~1058 */
#define RR    0.2f

typedef unsigned long long u64;

__device__ float g_ent[128];
__device__ unsigned int g_barrier;

__device__ __forceinline__ u64 fma2(u64 a, u64 b, u64 c) {
    u64 r;
    asm("fma.rn.f32x2 %0, %1, %2, %3;" : "=l"(r) : "l"(a), "l"(b), "l"(c));
    return r;
}
__device__ __forceinline__ unsigned int lo32(u64 v) { return (unsigned int)v; }
__device__ __forceinline__ unsigned int hi32(u64 v) { return (unsigned int)(v >> 32); }
// (hi of x, lo of y) -> packed f32x2 {lo=hi32(x), hi=lo32(y)}
__device__ __forceinline__ u64 mkodd(u64 x, u64 y) {
    return (u64)hi32(x) | ((u64)lo32(y) << 32);
}

// Self-contained unit: chunk c (k = k0..k0+31) of 4 diagonals dbase..dbase+3.
// 34 booleans per diagonal (j = 0..33); MSB-first acc, ext bits 31/30 = b32/b33.
// Boolean = sign( (a-b)^2 - Rs2 ), computed 2-at-a-time with fma.rn.f32x2:
//   d2 = fma2(w2, -1, a2) ; u2 = fma2(d2, d2, -Rs2) -> 1 fma-pipe op per pair.
__device__ __forceinline__ void unit_count(const float* __restrict__ xs, int k0, int dbase,
                                           int remBase, float Rs2, u64 NEG1, u64 NRS2,
                                           unsigned int& cm, unsigned int& cm1) {
    const u64* __restrict__ a2p = reinterpret_cast<const u64*>(xs + k0);           // 8B aligned
    const u64* __restrict__ ep  = reinterpret_cast<const u64*>(xs + k0 + dbase - 1); // 8B aligned
    unsigned int acc0 = 0, acc1 = 0, acc2 = 0, acc3 = 0;

    // rolling even-pair stream: e1 = Beven[2q+1]; oLast = Bodd[2q]
    u64 e0 = ep[0];
    u64 e1 = ep[1];
    u64 oL = mkodd(e0, e1);        // Bodd[0]

    #pragma unroll
    for (int q = 0; q < 8; q++) {
        u64 A0 = a2p[2 * q];           // (a[4q],   a[4q+1])
        u64 A1 = a2p[2 * q + 1];       // (a[4q+2], a[4q+3])
        u64 e2 = ep[2 * q + 2];
        u64 e3 = ep[2 * q + 3];
        u64 o1 = mkodd(e1, e2);        // Bodd[2q+1]
        u64 o2 = mkodd(e2, e3);        // Bodd[2q+2]

        // s = 0: starts 4q+1 (odd: oL), 4q+3 (odd: o1)
        {
            u64 d = fma2(oL, NEG1, A0); u64 u = fma2(d, d, NRS2);
            acc0 = __funnelshift_l(lo32(u), acc0, 1);
            acc0 = __funnelshift_l(hi32(u), acc0, 1);
            d = fma2(o1, NEG1, A1); u = fma2(d, d, NRS2);
            acc0 = __funnelshift_l(lo32(u), acc0, 1);
            acc0 = __funnelshift_l(hi32(u), acc0, 1);
        }
        // s = 1: starts 4q+2 (even: e1), 4q+4 (even: e2)
        {
            u64 d = fma2(e1, NEG1, A0); u64 u = fma2(d, d, NRS2);
            acc1 = __funnelshift_l(lo32(u), acc1, 1);
            acc1 = __funnelshift_l(hi32(u), acc1, 1);
            d = fma2(e2, NEG1, A1); u = fma2(d, d, NRS2);
            acc1 = __funnelshift_l(lo32(u), acc1, 1);
            acc1 = __funnelshift_l(hi32(u), acc1, 1);
        }
        // s = 2: starts 4q+3 (odd: o1), 4q+5 (odd: o2)
        {
            u64 d = fma2(o1, NEG1, A0); u64 u = fma2(d, d, NRS2);
            acc2 = __funnelshift_l(lo32(u), acc2, 1);
            acc2 = __funnelshift_l(hi32(u), acc2, 1);
            d = fma2(o2, NEG1, A1); u = fma2(d, d, NRS2);
            acc2 = __funnelshift_l(lo32(u), acc2, 1);
            acc2 = __funnelshift_l(hi32(u), acc2, 1);
        }
        // s = 3: starts 4q+4 (even: e2), 4q+6 (even: e3)
        {
            u64 d = fma2(e2, NEG1, A0); u64 u = fma2(d, d, NRS2);
            acc3 = __funnelshift_l(lo32(u), acc3, 1);
            acc3 = __funnelshift_l(hi32(u), acc3, 1);
            d = fma2(e3, NEG1, A1); u = fma2(d, d, NRS2);
            acc3 = __funnelshift_l(lo32(u), acc3, 1);
            acc3 = __funnelshift_l(hi32(u), acc3, 1);
        }
        e1 = e3; oL = o2;
    }

    // epilogue: j = 32, 33 (scalar)
    const float a32 = xs[k0 + 32];
    const float a33 = xs[k0 + 33];
    unsigned int acc[4] = {acc0, acc1, acc2, acc3};
    unsigned int ext[4];
    #pragma unroll
    for (int s = 0; s < 4; s++) {
        float W33 = xs[k0 + dbase + 32 + s];     // flat window index 33+s
        float W34 = xs[k0 + dbase + 33 + s];     // flat window index 34+s
        float d32 = a32 - W33;
        float d33 = a33 - W34;
        float u32 = fmaf(d32, d32, -Rs2);
        float u33 = fmaf(d33, d33, -Rs2);
        ext[s] = (__float_as_uint(u32) & 0x80000000u)
               | ((__float_as_uint(u33) >> 1) & 0x40000000u);
    }
    // count valid pairs k = k0 + j, j in [0, min(32, remBase - s))
    #pragma unroll
    for (int s = 0; s < 4; s++) {
        int rem = remBase - s;
        unsigned int mask = (rem >= 32) ? 0xffffffffu
                          : ((rem <= 0) ? 0u : (0xffffffffu << (32 - rem)));
        unsigned int S1 = __funnelshift_l(ext[s], acc[s], 1);
        unsigned int S2 = __funnelshift_l(ext[s], acc[s], 2);
        unsigned int mm = acc[s] & S1 & mask;
        cm  += __popc(mm);
        cm1 += __popc(mm & S2);
    }
}

__global__ __launch_bounds__(1024, 1)
void sampen_kernel(const float* __restrict__ pred, const float* __restrict__ tgt,
                   float* __restrict__ out) {
    __shared__ __align__(16) float xs[PAD];
    __shared__ double redA[32], redB[32];
    __shared__ unsigned int redc[32], redc1[32];
    __shared__ float s_thresh2;

    const int s   = blockIdx.x;
    const int tid = threadIdx.x;
    const float* src = (s < 64) ? (pred + (size_t)s * T_LEN)
                                : (tgt  + (size_t)(s - 64) * T_LEN);

    // ---- load raw signal + zero pad ----
    float v = src[tid];
    xs[tid] = v;
    for (int i = T_LEN + tid; i < PAD; i += 1024) xs[i] = 0.0f;

    // ---- std (ddof=1) in double; mean cancels inside |xi-xj|:
    //      squared scaled threshold Rs2 = (R*(std+eps))^2 ----
    double ls  = (double)v;
    double ls2 = (double)v * (double)v;
    #pragma unroll
    for (int o = 16; o > 0; o >>= 1) {
        ls  += __shfl_down_sync(0xffffffffu, ls,  o);
        ls2 += __shfl_down_sync(0xffffffffu, ls2, o);
    }
    if ((tid & 31) == 0) { redA[tid >> 5] = ls; redB[tid >> 5] = ls2; }
    __syncthreads();
    if (tid == 0) {
        double S = 0.0, S2 = 0.0;
        #pragma unroll
        for (int w = 0; w < 32; w++) { S += redA[w]; S2 += redB[w]; }
        double var = (S2 - S * S / (double)T_LEN) / (double)(T_LEN - 1);
        double sd  = sqrt(var);
        double rs  = (double)RR * (sd + 1e-8);
        s_thresh2  = (float)(rs * rs);
    }
    __syncthreads();
    const float Rs2 = s_thresh2;
    const u64 NEG1 = 0xBF800000BF800000ull;               // (-1.0f, -1.0f)
    const unsigned int nr = __float_as_uint(-Rs2);
    const u64 NRS2 = (u64)nr | ((u64)nr << 32);           // (-Rs2, -Rs2)

    // ---- upper-triangle counting: 4-diagonal groups, self-contained chunk units ----
    // Pair (P, 255-P): exactly 33 units. Thread (P = tid&127, sg = tid>>7) owns
    // units [g0, g1); sg warp-uniform -> uniform trips; A/B choice is a per-lane select.
    const int P  = tid & 127;
    const int sg = tid >> 7;           // warp-uniform
    const int dA = 4 * P + 1;
    const int LA = NN - dA;            // 1021 - 4P
    const int dB = 1021 - 4 * P;       // partner group 255-P
    const int LB = NN - dB;            // 4P + 1
    const int CA = (LA + 31) >> 5;
    const int g0 = (sg * 33) >> 3;
    const int g1 = ((sg + 1) * 33) >> 3;

    unsigned int cm = 0, cm1 = 0;
    for (int j = g0; j < g1; j++) {
        bool inA  = (j < CA);
        int dbase = inA ? dA : dB;
        int c     = inA ? j  : j - CA;
        int Lb    = inA ? LA : LB;
        int k0    = c << 5;
        unit_count(xs, k0, dbase, Lb - k0, Rs2, NEG1, NRS2, cm, cm1);
    }

    // ---- reduce counts ----
    #pragma unroll
    for (int o = 16; o > 0; o >>= 1) {
        cm  += __shfl_down_sync(0xffffffffu, cm,  o);
        cm1 += __shfl_down_sync(0xffffffffu, cm1, o);
    }
    if ((tid & 31) == 0) { redc[tid >> 5] = cm; redc1[tid >> 5] = cm1; }
    __syncthreads();

    if (tid == 0) {
        unsigned int tm = 0, tm1 = 0;
        #pragma unroll
        for (int w = 0; w < 32; w++) { tm += redc[w]; tm1 += redc1[w]; }
        // symmetric matrix + zero diagonal: matches = NN + 2*upper
        unsigned int matches_m  = (unsigned int)NN + 2u * tm;
        unsigned int matches_m1 = (unsigned int)NN + 2u * tm1;
        float ratio = (float)matches_m1 / (float)matches_m;   // matches_m >= NN > 0
        ratio = fmaxf(ratio, 1e-30f);
        g_ent[s] = -logf(ratio);

        // ---- fused finalize: last block computes the MSE ----
        __threadfence();
        unsigned int old = atomicAdd(&g_barrier, 1);
        if (old == 127u) {
            g_barrier = 0;            // reset for next graph replay
            __threadfence();          // make all g_ent writes visible
            float acc = 0.0f;
            #pragma unroll
            for (int i = 0; i < 64; i++) {
                float dp = __ldcg(&g_ent[i]);
                float dt = __ldcg(&g_ent[64 + i]);
                float dd = dp - dt;
                acc += dd * dd;
            }
            out[0] = acc * (1.0f / 64.0f);
        }
    }
}

extern "C" void kernel_launch(void* const* d_in, const int* in_sizes, int n_in,
                              void* d_out, int out_size) {
    const float* pred = (const float*)d_in[0];
    const float* tgt  = (const float*)d_in[1];
    float* out = (float*)d_out;
    sampen_kernel<<<128, 1024>>>(pred, tgt, out);
}

// round 9
// speedup vs baseline: 1.2743x; 1.0113x over previous
#include <cuda_runtime.h>
#include <math.h>

#define T_LEN 1024
#define NN    1022            /* templates */
#define PAD   1104            /* max smem read index ~1058 */
#define RR    0.2f
#define NTHR  768
#define NWARP (NTHR / 32)
#define NSLOT 6               /* sg slots = NTHR/128 */

typedef unsigned long long u64;

__device__ float g_ent[128];
__device__ unsigned int g_barrier;

__device__ __forceinline__ u64 fma2(u64 a, u64 b, u64 c) {
    u64 r;
    asm("fma.rn.f32x2 %0, %1, %2, %3;" : "=l"(r) : "l"(a), "l"(b), "l"(c));
    return r;
}
__device__ __forceinline__ unsigned int lo32(u64 v) { return (unsigned int)v; }
__device__ __forceinline__ unsigned int hi32(u64 v) { return (unsigned int)(v >> 32); }
// (hi of x, lo of y) -> packed f32x2 {lo=hi32(x), hi=lo32(y)}
__device__ __forceinline__ u64 mkodd(u64 x, u64 y) {
    return (u64)hi32(x) | ((u64)lo32(y) << 32);
}

// Self-contained unit: chunk c (k = k0..k0+31) of 4 diagonals dbase..dbase+3.
// 34 booleans per diagonal (j = 0..33); MSB-first acc, ext bits 31/30 = b32/b33.
// Boolean = sign( (a-b)^2 - Rs2 ), computed 2-at-a-time with fma.rn.f32x2:
//   d2 = fma2(w2, -1, a2) ; u2 = fma2(d2, d2, -Rs2) -> 1 fma-pipe op per pair.
__device__ __forceinline__ void unit_count(const float* __restrict__ xs, int k0, int dbase,
                                           int remBase, float Rs2, u64 NEG1, u64 NRS2,
                                           unsigned int& cm, unsigned int& cm1) {
    const u64* __restrict__ a2p = reinterpret_cast<const u64*>(xs + k0);             // 8B aligned
    const u64* __restrict__ ep  = reinterpret_cast<const u64*>(xs + k0 + dbase - 1); // 8B aligned
    unsigned int acc0 = 0, acc1 = 0, acc2 = 0, acc3 = 0;

    // rolling even-pair stream: e1 = Beven[2q+1]; oL = Bodd[2q]
    u64 e0 = ep[0];
    u64 e1 = ep[1];
    u64 oL = mkodd(e0, e1);        // Bodd[0]

    #pragma unroll
    for (int q = 0; q < 8; q++) {
        u64 A0 = a2p[2 * q];           // (a[4q],   a[4q+1])
        u64 A1 = a2p[2 * q + 1];       // (a[4q+2], a[4q+3])
        u64 e2 = ep[2 * q + 2];
        u64 e3 = ep[2 * q + 3];
        u64 o1 = mkodd(e1, e2);        // Bodd[2q+1]
        u64 o2 = mkodd(e2, e3);        // Bodd[2q+2]

        // s = 0: starts 4q+1 (odd: oL), 4q+3 (odd: o1)
        {
            u64 d = fma2(oL, NEG1, A0); u64 u = fma2(d, d, NRS2);
            acc0 = __funnelshift_l(lo32(u), acc0, 1);
            acc0 = __funnelshift_l(hi32(u), acc0, 1);
            d = fma2(o1, NEG1, A1); u = fma2(d, d, NRS2);
            acc0 = __funnelshift_l(lo32(u), acc0, 1);
            acc0 = __funnelshift_l(hi32(u), acc0, 1);
        }
        // s = 1: starts 4q+2 (even: e1), 4q+4 (even: e2)
        {
            u64 d = fma2(e1, NEG1, A0); u64 u = fma2(d, d, NRS2);
            acc1 = __funnelshift_l(lo32(u), acc1, 1);
            acc1 = __funnelshift_l(hi32(u), acc1, 1);
            d = fma2(e2, NEG1, A1); u = fma2(d, d, NRS2);
            acc1 = __funnelshift_l(lo32(u), acc1, 1);
            acc1 = __funnelshift_l(hi32(u), acc1, 1);
        }
        // s = 2: starts 4q+3 (odd: o1), 4q+5 (odd: o2)
        {
            u64 d = fma2(o1, NEG1, A0); u64 u = fma2(d, d, NRS2);
            acc2 = __funnelshift_l(lo32(u), acc2, 1);
            acc2 = __funnelshift_l(hi32(u), acc2, 1);
            d = fma2(o2, NEG1, A1); u = fma2(d, d, NRS2);
            acc2 = __funnelshift_l(lo32(u), acc2, 1);
            acc2 = __funnelshift_l(hi32(u), acc2, 1);
        }
        // s = 3: starts 4q+4 (even: e2), 4q+6 (even: e3)
        {
            u64 d = fma2(e2, NEG1, A0); u64 u = fma2(d, d, NRS2);
            acc3 = __funnelshift_l(lo32(u), acc3, 1);
            acc3 = __funnelshift_l(hi32(u), acc3, 1);
            d = fma2(e3, NEG1, A1); u = fma2(d, d, NRS2);
            acc3 = __funnelshift_l(lo32(u), acc3, 1);
            acc3 = __funnelshift_l(hi32(u), acc3, 1);
        }
        e1 = e3; oL = o2;
    }

    // epilogue: j = 32, 33 (scalar)
    const float a32 = xs[k0 + 32];
    const float a33 = xs[k0 + 33];
    unsigned int acc[4] = {acc0, acc1, acc2, acc3};
    unsigned int ext[4];
    #pragma unroll
    for (int s = 0; s < 4; s++) {
        float W33 = xs[k0 + dbase + 32 + s];     // flat window index 33+s
        float W34 = xs[k0 + dbase + 33 + s];     // flat window index 34+s
        float d32 = a32 - W33;
        float d33 = a33 - W34;
        float u32 = fmaf(d32, d32, -Rs2);
        float u33 = fmaf(d33, d33, -Rs2);
        ext[s] = (__float_as_uint(u32) & 0x80000000u)
               | ((__float_as_uint(u33) >> 1) & 0x40000000u);
    }
    // count valid pairs k = k0 + j, j in [0, min(32, remBase - s))
    #pragma unroll
    for (int s = 0; s < 4; s++) {
        int rem = remBase - s;
        unsigned int mask = (rem >= 32) ? 0xffffffffu
                          : ((rem <= 0) ? 0u : (0xffffffffu << (32 - rem)));
        unsigned int S1 = __funnelshift_l(ext[s], acc[s], 1);
        unsigned int S2 = __funnelshift_l(ext[s], acc[s], 2);
        unsigned int mm = acc[s] & S1 & mask;
        cm  += __popc(mm);
        cm1 += __popc(mm & S2);
    }
}

__global__ __launch_bounds__(NTHR, 1)
void sampen_kernel(const float* __restrict__ pred, const float* __restrict__ tgt,
                   float* __restrict__ out) {
    __shared__ __align__(16) float xs[PAD];
    __shared__ double redA[NWARP], redB[NWARP];
    __shared__ unsigned int redc[NWARP], redc1[NWARP];
    __shared__ float s_thresh2;

    const int s   = blockIdx.x;
    const int tid = threadIdx.x;
    const float* src = (s < 64) ? (pred + (size_t)s * T_LEN)
                                : (tgt  + (size_t)(s - 64) * T_LEN);

    // ---- load raw signal + zero pad ----
    float v0 = src[tid];
    float v1 = (tid + NTHR < T_LEN) ? src[tid + NTHR] : 0.0f;
    xs[tid] = v0;
    if (tid + NTHR < T_LEN) xs[tid + NTHR] = v1;
    for (int i = T_LEN + tid; i < PAD; i += NTHR) xs[i] = 0.0f;

    // ---- std (ddof=1) in double; mean cancels inside |xi-xj|:
    //      squared scaled threshold Rs2 = (R*(std+eps))^2 ----
    double ls  = (double)v0 + (double)v1;
    double ls2 = (double)v0 * (double)v0 + (double)v1 * (double)v1;
    #pragma unroll
    for (int o = 16; o > 0; o >>= 1) {
        ls  += __shfl_down_sync(0xffffffffu, ls,  o);
        ls2 += __shfl_down_sync(0xffffffffu, ls2, o);
    }
    if ((tid & 31) == 0) { redA[tid >> 5] = ls; redB[tid >> 5] = ls2; }
    __syncthreads();
    if (tid == 0) {
        double S = 0.0, S2 = 0.0;
        #pragma unroll
        for (int w = 0; w < NWARP; w++) { S += redA[w]; S2 += redB[w]; }
        double var = (S2 - S * S / (double)T_LEN) / (double)(T_LEN - 1);
        double sd  = sqrt(var);
        double rs  = (double)RR * (sd + 1e-8);
        s_thresh2  = (float)(rs * rs);
    }
    __syncthreads();
    const float Rs2 = s_thresh2;
    const u64 NEG1 = 0xBF800000BF800000ull;               // (-1.0f, -1.0f)
    const unsigned int nr = __float_as_uint(-Rs2);
    const u64 NRS2 = (u64)nr | ((u64)nr << 32);           // (-Rs2, -Rs2)

    // ---- upper-triangle counting: 4-diagonal groups, self-contained chunk units ----
    // Pair (P, 255-P): exactly 33 units. Thread (P = tid&127, sg = tid>>7 in [0,6))
    // owns units [g0, g1); sg warp-uniform -> uniform trips; A/B is a per-lane select.
    const int P  = tid & 127;
    const int sg = tid >> 7;           // warp-uniform, 0..5
    const int dA = 4 * P + 1;
    const int LA = NN - dA;            // 1021 - 4P
    const int dB = 1021 - 4 * P;       // partner group 255-P
    const int LB = NN - dB;            // 4P + 1
    const int CA = (LA + 31) >> 5;
    const int g0 = (sg * 33) / NSLOT;
    const int g1 = ((sg + 1) * 33) / NSLOT;

    unsigned int cm = 0, cm1 = 0;
    for (int j = g0; j < g1; j++) {
        bool inA  = (j < CA);
        int dbase = inA ? dA : dB;
        int c     = inA ? j  : j - CA;
        int Lb    = inA ? LA : LB;
        int k0    = c << 5;
        unit_count(xs, k0, dbase, Lb - k0, Rs2, NEG1, NRS2, cm, cm1);
    }

    // ---- reduce counts ----
    #pragma unroll
    for (int o = 16; o > 0; o >>= 1) {
        cm  += __shfl_down_sync(0xffffffffu, cm,  o);
        cm1 += __shfl_down_sync(0xffffffffu, cm1, o);
    }
    if ((tid & 31) == 0) { redc[tid >> 5] = cm; redc1[tid >> 5] = cm1; }
    __syncthreads();

    if (tid == 0) {
        unsigned int tm = 0, tm1 = 0;
        #pragma unroll
        for (int w = 0; w < NWARP; w++) { tm += redc[w]; tm1 += redc1[w]; }
        // symmetric matrix + zero diagonal: matches = NN + 2*upper
        unsigned int matches_m  = (unsigned int)NN + 2u * tm;
        unsigned int matches_m1 = (unsigned int)NN + 2u * tm1;
        float ratio = (float)matches_m1 / (float)matches_m;   // matches_m >= NN > 0
        ratio = fmaxf(ratio, 1e-30f);
        g_ent[s] = -logf(ratio);

        // ---- fused finalize: last block computes the MSE ----
        __threadfence();
        unsigned int old = atomicAdd(&g_barrier, 1);
        if (old == 127u) {
            g_barrier = 0;            // reset for next graph replay
            __threadfence();          // make all g_ent writes visible
            float acc = 0.0f;
            #pragma unroll
            for (int i = 0; i < 64; i++) {
                float dp = __ldcg(&g_ent[i]);
                float dt = __ldcg(&g_ent[64 + i]);
                float dd = dp - dt;
                acc += dd * dd;
            }
            out[0] = acc * (1.0f / 64.0f);
        }
    }
}

extern "C" void kernel_launch(void* const* d_in, const int* in_sizes, int n_in,
                              void* d_out, int out_size) {
    const float* pred = (const float*)d_in[0];
    const float* tgt  = (const float*)d_in[1];
    float* out = (float*)d_out;
    sampen_kernel<<<128, NTHR>>>(pred, tgt, out);
}

// round 10
// speedup vs baseline: 1.3482x; 1.0580x over previous
#include <cuda_runtime.h>
#include <math.h>

#define T_LEN 1024
#define NN    1022            /* templates */
#define PAD   1104            /* max smem read index ~1058 */
#define RR    0.2f
#define NTHR  512
#define NWARP (NTHR / 32)

typedef unsigned long long u64;

__device__ float g_ent[128];
__device__ unsigned int g_barrier;

__device__ __forceinline__ u64 fma2(u64 a, u64 b, u64 c) {
    u64 r;
    asm("fma.rn.f32x2 %0, %1, %2, %3;" : "=l"(r) : "l"(a), "l"(b), "l"(c));
    return r;
}
__device__ __forceinline__ unsigned int lo32(u64 v) { return (unsigned int)v; }
__device__ __forceinline__ unsigned int hi32(u64 v) { return (unsigned int)(v >> 32); }
// (hi of x, lo of y) -> packed f32x2 {lo=hi32(x), hi=lo32(y)}
__device__ __forceinline__ u64 mkodd(u64 x, u64 y) {
    return (u64)hi32(x) | ((u64)lo32(y) << 32);
}

// ---- single self-contained unit (tail use): chunk k0..k0+31 of diagonals
// dbase..dbase+3; 34 booleans/diagonal, MSB-first, sign((a-b)^2 - Rs2). ----
__device__ __forceinline__ void unit_count(const float* __restrict__ xs, int k0, int dbase,
                                           int remBase, float Rs2, u64 NEG1, u64 NRS2,
                                           unsigned int& cm, unsigned int& cm1) {
    const u64* __restrict__ a2p = reinterpret_cast<const u64*>(xs + k0);
    const u64* __restrict__ ep  = reinterpret_cast<const u64*>(xs + k0 + dbase - 1);
    unsigned int acc[4] = {0, 0, 0, 0};
    u64 e0 = ep[0];
    u64 e1 = ep[1];
    u64 oL = mkodd(e0, e1);
    #pragma unroll
    for (int q = 0; q < 8; q++) {
        u64 A0 = a2p[2 * q];
        u64 A1 = a2p[2 * q + 1];
        u64 e2 = ep[2 * q + 2];
        u64 e3 = ep[2 * q + 3];
        u64 o1 = mkodd(e1, e2);
        u64 o2 = mkodd(e2, e3);
        u64 W0[4] = {oL, e1, o1, e2};
        u64 W1[4] = {o1, e2, o2, e3};
        #pragma unroll
        for (int s = 0; s < 4; s++) {
            u64 d = fma2(W0[s], NEG1, A0); u64 u = fma2(d, d, NRS2);
            acc[s] = __funnelshift_l(lo32(u), acc[s], 1);
            acc[s] = __funnelshift_l(hi32(u), acc[s], 1);
            d = fma2(W1[s], NEG1, A1); u = fma2(d, d, NRS2);
            acc[s] = __funnelshift_l(lo32(u), acc[s], 1);
            acc[s] = __funnelshift_l(hi32(u), acc[s], 1);
        }
        e1 = e3; oL = o2;
    }
    const float a32 = xs[k0 + 32];
    const float a33 = xs[k0 + 33];
    #pragma unroll
    for (int s = 0; s < 4; s++) {
        float W33 = xs[k0 + dbase + 32 + s];
        float W34 = xs[k0 + dbase + 33 + s];
        float d32 = a32 - W33;
        float d33 = a33 - W34;
        float u32 = fmaf(d32, d32, -Rs2);
        float u33 = fmaf(d33, d33, -Rs2);
        unsigned int ext = (__float_as_uint(u32) & 0x80000000u)
                         | ((__float_as_uint(u33) >> 1) & 0x40000000u);
        int rem = remBase - s;
        unsigned int mask = (rem >= 32) ? 0xffffffffu
                          : ((rem <= 0) ? 0u : (0xffffffffu << (32 - rem)));
        unsigned int S1 = __funnelshift_l(ext, acc[s], 1);
        unsigned int S2 = __funnelshift_l(ext, acc[s], 2);
        unsigned int mm = acc[s] & S1 & mask;
        cm  += __popc(mm);
        cm1 += __popc(mm & S2);
    }
}

// ---- two interleaved independent units: doubles ILP (2 fma2 streams, 8 acc
// chains, 2 LDS streams) to cover fixed-op + LDS latency per warp. ----
__device__ __forceinline__ void unit2_count(const float* __restrict__ xs,
                                            int k0a, int dba, int remA,
                                            int k0b, int dbb, int remB,
                                            float Rs2, u64 NEG1, u64 NRS2,
                                            unsigned int& cm, unsigned int& cm1) {
    const u64* __restrict__ a2pA = reinterpret_cast<const u64*>(xs + k0a);
    const u64* __restrict__ epA  = reinterpret_cast<const u64*>(xs + k0a + dba - 1);
    const u64* __restrict__ a2pB = reinterpret_cast<const u64*>(xs + k0b);
    const u64* __restrict__ epB  = reinterpret_cast<const u64*>(xs + k0b + dbb - 1);
    unsigned int accA[4] = {0, 0, 0, 0};
    unsigned int accB[4] = {0, 0, 0, 0};
    u64 e1A, oLA, e1B, oLB;
    { u64 e0 = epA[0]; e1A = epA[1]; oLA = mkodd(e0, e1A); }
    { u64 e0 = epB[0]; e1B = epB[1]; oLB = mkodd(e0, e1B); }
    #pragma unroll
    for (int q = 0; q < 8; q++) {
        // loads for both streams up front (independent; ptxas can batch)
        u64 A0a = a2pA[2 * q];
        u64 A1a = a2pA[2 * q + 1];
        u64 e2a = epA[2 * q + 2];
        u64 e3a = epA[2 * q + 3];
        u64 A0b = a2pB[2 * q];
        u64 A1b = a2pB[2 * q + 1];
        u64 e2b = epB[2 * q + 2];
        u64 e3b = epB[2 * q + 3];
        u64 o1a = mkodd(e1A, e2a);
        u64 o2a = mkodd(e2a, e3a);
        u64 o1b = mkodd(e1B, e2b);
        u64 o2b = mkodd(e2b, e3b);
        u64 W0a[4] = {oLA, e1A, o1a, e2a};
        u64 W1a[4] = {o1a, e2a, o2a, e3a};
        u64 W0b[4] = {oLB, e1B, o1b, e2b};
        u64 W1b[4] = {o1b, e2b, o2b, e3b};
        #pragma unroll
        for (int s = 0; s < 4; s++) {
            u64 da = fma2(W0a[s], NEG1, A0a); u64 ua = fma2(da, da, NRS2);
            u64 db = fma2(W0b[s], NEG1, A0b); u64 ub = fma2(db, db, NRS2);
            accA[s] = __funnelshift_l(lo32(ua), accA[s], 1);
            accA[s] = __funnelshift_l(hi32(ua), accA[s], 1);
            accB[s] = __funnelshift_l(lo32(ub), accB[s], 1);
            accB[s] = __funnelshift_l(hi32(ub), accB[s], 1);
            da = fma2(W1a[s], NEG1, A1a); ua = fma2(da, da, NRS2);
            db = fma2(W1b[s], NEG1, A1b); ub = fma2(db, db, NRS2);
            accA[s] = __funnelshift_l(lo32(ua), accA[s], 1);
            accA[s] = __funnelshift_l(hi32(ua), accA[s], 1);
            accB[s] = __funnelshift_l(lo32(ub), accB[s], 1);
            accB[s] = __funnelshift_l(hi32(ub), accB[s], 1);
        }
        e1A = e3a; oLA = o2a;
        e1B = e3b; oLB = o2b;
    }
    // epilogues + counting (both streams)
    {
        const float a32 = xs[k0a + 32];
        const float a33 = xs[k0a + 33];
        #pragma unroll
        for (int s = 0; s < 4; s++) {
            float W33 = xs[k0a + dba + 32 + s];
            float W34 = xs[k0a + dba + 33 + s];
            float d32 = a32 - W33;
            float d33 = a33 - W34;
            float u32 = fmaf(d32, d32, -Rs2);
            float u33 = fmaf(d33, d33, -Rs2);
            unsigned int ext = (__float_as_uint(u32) & 0x80000000u)
                             | ((__float_as_uint(u33) >> 1) & 0x40000000u);
            int rem = remA - s;
            unsigned int mask = (rem >= 32) ? 0xffffffffu
                              : ((rem <= 0) ? 0u : (0xffffffffu << (32 - rem)));
            unsigned int S1 = __funnelshift_l(ext, accA[s], 1);
            unsigned int S2 = __funnelshift_l(ext, accA[s], 2);
            unsigned int mm = accA[s] & S1 & mask;
            cm  += __popc(mm);
            cm1 += __popc(mm & S2);
        }
    }
    {
        const float a32 = xs[k0b + 32];
        const float a33 = xs[k0b + 33];
        #pragma unroll
        for (int s = 0; s < 4; s++) {
            float W33 = xs[k0b + dbb + 32 + s];
            float W34 = xs[k0b + dbb + 33 + s];
            float d32 = a32 - W33;
            float d33 = a33 - W34;
            float u32 = fmaf(d32, d32, -Rs2);
            float u33 = fmaf(d33, d33, -Rs2);
            unsigned int ext = (__float_as_uint(u32) & 0x80000000u)
                             | ((__float_as_uint(u33) >> 1) & 0x40000000u);
            int rem = remB - s;
            unsigned int mask = (rem >= 32) ? 0xffffffffu
                              : ((rem <= 0) ? 0u : (0xffffffffu << (32 - rem)));
            unsigned int S1 = __funnelshift_l(ext, accB[s], 1);
            unsigned int S2 = __funnelshift_l(ext, accB[s], 2);
            unsigned int mm = accB[s] & S1 & mask;
            cm  += __popc(mm);
            cm1 += __popc(mm & S2);
        }
    }
}

__global__ __launch_bounds__(NTHR, 1)
void sampen_kernel(const float* __restrict__ pred, const float* __restrict__ tgt,
                   float* __restrict__ out) {
    __shared__ __align__(16) float xs[PAD];
    __shared__ double redA[NWARP], redB[NWARP];
    __shared__ unsigned int redc[NWARP], redc1[NWARP];
    __shared__ float s_thresh2;

    const int s   = blockIdx.x;
    const int tid = threadIdx.x;
    const float* src = (s < 64) ? (pred + (size_t)s * T_LEN)
                                : (tgt  + (size_t)(s - 64) * T_LEN);

    // ---- load raw signal + zero pad ----
    float v0 = src[tid];
    float v1 = src[tid + NTHR];
    xs[tid]        = v0;
    xs[tid + NTHR] = v1;
    for (int i = T_LEN + tid; i < PAD; i += NTHR) xs[i] = 0.0f;

    // ---- std (ddof=1) in double; mean cancels inside |xi-xj|:
    //      squared scaled threshold Rs2 = (R*(std+eps))^2 ----
    double ls  = (double)v0 + (double)v1;
    double ls2 = (double)v0 * (double)v0 + (double)v1 * (double)v1;
    #pragma unroll
    for (int o = 16; o > 0; o >>= 1) {
        ls  += __shfl_down_sync(0xffffffffu, ls,  o);
        ls2 += __shfl_down_sync(0xffffffffu, ls2, o);
    }
    if ((tid & 31) == 0) { redA[tid >> 5] = ls; redB[tid >> 5] = ls2; }
    __syncthreads();
    if (tid == 0) {
        double S = 0.0, S2 = 0.0;
        #pragma unroll
        for (int w = 0; w < NWARP; w++) { S += redA[w]; S2 += redB[w]; }
        double var = (S2 - S * S / (double)T_LEN) / (double)(T_LEN - 1);
        double sd  = sqrt(var);
        double rs  = (double)RR * (sd + 1e-8);
        s_thresh2  = (float)(rs * rs);
    }
    __syncthreads();
    const float Rs2 = s_thresh2;
    const u64 NEG1 = 0xBF800000BF800000ull;               // (-1.0f, -1.0f)
    const unsigned int nr = __float_as_uint(-Rs2);
    const u64 NRS2 = (u64)nr | ((u64)nr << 32);           // (-Rs2, -Rs2)

    // ---- upper-triangle counting: 4-diagonal groups, 2-unit-interleaved ----
    // Pair (P, 255-P): exactly 33 units. Thread (P = tid&127, sg = tid>>7 in [0,4))
    // owns units [g0, g1): counts {8,8,8,9}. Units processed 2 at a time (ILP),
    // with a single-unit tail only for sg == 3 (warp-uniform).
    const int P  = tid & 127;
    const int sg = tid >> 7;           // warp-uniform, 0..3
    const int dA = 4 * P + 1;
    const int LA = NN - dA;            // 1021 - 4P
    const int dB = 1021 - 4 * P;       // partner group 255-P
    const int LB = NN - dB;            // 4P + 1
    const int CA = (LA + 31) >> 5;
    const int g0 = (sg * 33) >> 2;
    const int g1 = ((sg + 1) * 33) >> 2;

    unsigned int cm = 0, cm1 = 0;
    int j = g0;
    for (; j + 1 < g1; j += 2) {
        bool inA0  = (j < CA);
        int dbase0 = inA0 ? dA : dB;
        int c0     = inA0 ? j  : j - CA;
        int Lb0    = inA0 ? LA : LB;
        int jb     = j + 1;
        bool inA1  = (jb < CA);
        int dbase1 = inA1 ? dA : dB;
        int c1     = inA1 ? jb : jb - CA;
        int Lb1    = inA1 ? LA : LB;
        unit2_count(xs, c0 << 5, dbase0, Lb0 - (c0 << 5),
                        c1 << 5, dbase1, Lb1 - (c1 << 5),
                    Rs2, NEG1, NRS2, cm, cm1);
    }
    if (j < g1) {                       // only sg == 3 (warp-uniform)
        bool inA  = (j < CA);
        int dbase = inA ? dA : dB;
        int c     = inA ? j  : j - CA;
        int Lb    = inA ? LA : LB;
        unit_count(xs, c << 5, dbase, Lb - (c << 5), Rs2, NEG1, NRS2, cm, cm1);
    }

    // ---- reduce counts ----
    #pragma unroll
    for (int o = 16; o > 0; o >>= 1) {
        cm  += __shfl_down_sync(0xffffffffu, cm,  o);
        cm1 += __shfl_down_sync(0xffffffffu, cm1, o);
    }
    if ((tid & 31) == 0) { redc[tid >> 5] = cm; redc1[tid >> 5] = cm1; }
    __syncthreads();

    if (tid == 0) {
        unsigned int tm = 0, tm1 = 0;
        #pragma unroll
        for (int w = 0; w < NWARP; w++) { tm += redc[w]; tm1 += redc1[w]; }
        // symmetric matrix + zero diagonal: matches = NN + 2*upper
        unsigned int matches_m  = (unsigned int)NN + 2u * tm;
        unsigned int matches_m1 = (unsigned int)NN + 2u * tm1;
        float ratio = (float)matches_m1 / (float)matches_m;   // matches_m >= NN > 0
        ratio = fmaxf(ratio, 1e-30f);
        g_ent[s] = -logf(ratio);

        // ---- fused finalize: last block computes the MSE ----
        __threadfence();
        unsigned int old = atomicAdd(&g_barrier, 1);
        if (old == 127u) {
            g_barrier = 0;            // reset for next graph replay
            __threadfence();          // make all g_ent writes visible
            float acc = 0.0f;
            #pragma unroll
            for (int i = 0; i < 64; i++) {
                float dp = __ldcg(&g_ent[i]);
                float dt = __ldcg(&g_ent[64 + i]);
                float dd = dp - dt;
                acc += dd * dd;
            }
            out[0] = acc * (1.0f / 64.0f);
        }
    }
}

extern "C" void kernel_launch(void* const* d_in, const int* in_sizes, int n_in,
                              void* d_out, int out_size) {
    const float* pred = (const float*)d_in[0];
    const float* tgt  = (const float*)d_in[1];
    float* out = (float*)d_out;
    sampen_kernel<<<128, NTHR>>>(pred, tgt, out);
}